// round 11
// baseline (speedup 1.0000x reference)
#include <cuda_runtime.h>
#include <cstdint>

// ---------------- problem constants ----------------
#define NB    32
#define CIN   256
#define COUTC 256
#define TT    128
#define VV    25
#define KK    3
#define QQ    (TT*VV)       // 3200 pixels per n
#define QTOT  (NB*QQ)       // 102400
#define MTOT  768           // reduction dim m = (k,ci)
#define BN_EPS 1e-5f
#define CNT   (NB*TT*VV)

// ---------------- GEMM tiling ----------------
#define BM    128
#define BNQ   128
#define BK    32
#define NKC   24            // 768/32
#define NQT2  800           // 102400/128
#define NPART 3200

// fragment-order tiles, 3-stage pipeline
#define TILE_F  4096
#define NSTAGE  3
#define SMEM_GEMM (2*NSTAGE*TILE_F*4)   // 98304 bytes: A0..A2, X0..X2

typedef unsigned long long ull;

// ---------------- device scratch ----------------
// W2 fragment order: [R=c/16][K=m/8][quad=(c&7)*4+(m&3)][pos=(c>>3&1)+2*(m>>2&1)]
__device__ __align__(16) float g_W2[COUTC * MTOT];
// XA fragment order: [Nb=q/8][k16=m/16][(q&7)*16 + (m&3)*4 + (m>>3&1)*2 + (m>>2&1)]
__device__ __align__(16) float g_XA[(size_t)QTOT * MTOT];
__device__ __align__(16) float g_z [(size_t)NB * COUTC * QQ];
__device__ float g_zb  [COUTC * VV];
__device__ float g_psum[COUTC * NPART];
__device__ float g_psq [COUTC * NPART];
__device__ float g_ss  [2 * COUTC];

// ---------------- helpers ----------------
__device__ __forceinline__ uint32_t smem_u32(const void* p) {
    uint32_t a;
    asm("{ .reg .u64 t; cvta.to.shared.u64 t, %1; cvt.u32.u64 %0, t; }" : "=r"(a) : "l"(p));
    return a;
}
__device__ __forceinline__ ull pack2(float lo, float hi) {
    ull r; asm("mov.b64 %0, {%1,%2};" : "=l"(r) : "f"(lo), "f"(hi)); return r;
}
__device__ __forceinline__ void unpack2(ull a, float &lo, float &hi) {
    asm("mov.b64 {%0,%1}, %2;" : "=f"(lo), "=f"(hi) : "l"(a));
}
__device__ __forceinline__ ull fma2(ull a, ull b, ull c) {
    ull d; asm("fma.rn.f32x2 %0, %1, %2, %3;" : "=l"(d) : "l"(a), "l"(b), "l"(c)); return d;
}
__device__ __forceinline__ float totf32(float f) {
    uint32_t u; asm("cvt.rna.tf32.f32 %0, %1;" : "=r"(u) : "f"(f));
    return __uint_as_float(u);
}

#define CP_ASYNC16(dst, src) \
    asm volatile("cp.async.cg.shared.global [%0], [%1], 16;" :: "r"(dst), "l"(src))
#define CP_COMMIT() asm volatile("cp.async.commit_group;" ::: "memory")
#define CP_WAIT1()  asm volatile("cp.async.wait_group 1;"  ::: "memory")

__device__ __forceinline__ void mma_tf32(float* c, uint32_t a0, uint32_t a1, uint32_t a2,
                                         uint32_t a3, uint32_t b0, uint32_t b1) {
    asm volatile(
        "mma.sync.aligned.m16n8k8.row.col.f32.tf32.tf32.f32 "
        "{%0,%1,%2,%3}, {%4,%5,%6,%7}, {%8,%9}, {%0,%1,%2,%3};"
        : "+f"(c[0]), "+f"(c[1]), "+f"(c[2]), "+f"(c[3])
        : "r"(a0), "r"(a1), "r"(a2), "r"(a3), "r"(b0), "r"(b1));
}

// fragment position within an aligned 16-block of m
__host__ __device__ __forceinline__ int fragpos(int mlo) {
    return (mlo & 3) * 4 + ((mlo >> 3) & 1) * 2 + ((mlo >> 2) & 1);
}

// fragment-order index for W2: element (c, m)
__device__ __forceinline__ size_t w2f_idx(int c, int m) {
    return (((size_t)(c >> 4) * 96 + (m >> 3)) * 32 + (c & 7) * 4 + (m & 3)) * 4
           + ((c >> 3) & 1) + 2 * ((m >> 2) & 1);
}

// ---------------- kernel: W re-layout (tf32 + fragment order) ----------------
__global__ void k_w2(const float* __restrict__ W) {
    const int o = blockIdx.x;            // 0..767
    const int ci = threadIdx.x;
    const int c = o & 255, k = o >> 8;
    const int m = k * 256 + ci;
    g_W2[w2f_idx(c, m)] = totf32(W[o * 256 + ci]);
}

// ---------------- kernel: bias fold term ----------------
__global__ void k_zb(const float* __restrict__ A, const float* __restrict__ b) {
    const int w = blockIdx.x;
    const int c = threadIdx.x;
    float s = 0.f;
    for (int k = 0; k < KK; k++) {
        float sa = 0.f;
        for (int v = 0; v < VV; v++) sa += A[(k * VV + v) * VV + w];
        s += b[k * 256 + c] * sa;
    }
    g_zb[c * VV + w] = s;
}

// ---------------- kernel: fold adjacency into input ----------------
// Compute as before; stage per-k results in permuted smem; write coalesced 64B chunks.
#define ZPAD 260
__global__ __launch_bounds__(128) void k_prep(const float* __restrict__ x,
                                              const float* __restrict__ A) {
    __shared__ ull As2[KK][VV][13];
    __shared__ __align__(16) float zs[VV][ZPAD];

    const int bx = blockIdx.x;
    const int n = bx >> 7;
    const int t = bx & (TT - 1);
    const int tid = threadIdx.x;

    for (int i = tid; i < KK * VV * 13; i += 128) {
        int k = i / (VV * 13);
        int r = i - k * (VV * 13);
        int v = r / 13, j = r - v * 13;
        float lo = A[(k * VV + v) * VV + 2 * j];
        float hi = (2 * j + 1 < VV) ? A[(k * VV + v) * VV + 2 * j + 1] : 0.f;
        As2[k][v][j] = pack2(lo, hi);
    }

    float xa[VV], xb[VV];
    {
        const float* pa = x + ((size_t)(n * CIN + tid) * TT + t) * VV;
        const float* pb = x + ((size_t)(n * CIN + tid + 128) * TT + t) * VV;
        #pragma unroll
        for (int v = 0; v < VV; v++) { xa[v] = pa[v]; xb[v] = pb[v]; }
    }
    __syncthreads();

    const int qbase = n * QQ + t * VV;
    // permuted positions within the 256-m slab of one k
    const int fp = fragpos(tid & 15);
    const int pa = ((tid >> 4) << 4) + fp;        // m = tid      -> mb 0..7
    const int pb = pa + 128;                      // m = tid+128  -> mb 8..15

    for (int k = 0; k < KK; k++) {
        ull za[13], zq[13];
        #pragma unroll
        for (int j = 0; j < 13; j++) { za[j] = 0ull; zq[j] = 0ull; }
        for (int v = 0; v < VV; v++) {
            const ull a2 = pack2(xa[v], xa[v]);
            const ull b2 = pack2(xb[v], xb[v]);
            #pragma unroll
            for (int j = 0; j < 13; j++) {
                const ull m = As2[k][v][j];
                za[j] = fma2(a2, m, za[j]);
                zq[j] = fma2(b2, m, zq[j]);
            }
        }
        // phase B: tf32-round + permuted staging (conflict-free STS)
        #pragma unroll
        for (int j = 0; j < 13; j++) {
            float lo, hi;
            unpack2(za[j], lo, hi);
            zs[2 * j][pa] = totf32(lo);
            if (2 * j + 1 < VV) zs[2 * j + 1][pa] = totf32(hi);
            unpack2(zq[j], lo, hi);
            zs[2 * j][pb] = totf32(lo);
            if (2 * j + 1 < VV) zs[2 * j + 1][pb] = totf32(hi);
        }
        __syncthreads();
        // phase C: cooperative coalesced 64B-chunk writes
        for (int item = tid; item < VV * 16; item += 128) {
            const int mb = item / VV;            // 0..15
            const int q  = item - mb * VV;       // 0..24  (fastest across lanes)
            const int qg = qbase + q;
            const float4 v0 = *(const float4*)&zs[q][mb * 16 + 0];
            const float4 v1 = *(const float4*)&zs[q][mb * 16 + 4];
            const float4 v2 = *(const float4*)&zs[q][mb * 16 + 8];
            const float4 v3 = *(const float4*)&zs[q][mb * 16 + 12];
            float4* dst = (float4*)(g_XA + (size_t)(qg >> 3) * 6144
                                         + (size_t)(k * 16 + mb) * 128 + (qg & 7) * 16);
            dst[0] = v0; dst[1] = v1; dst[2] = v2; dst[3] = v3;
        }
        __syncthreads();
    }
}

// ---------------- kernel: warp-MMA tf32 GEMM (3-stage) + fused epilogue ----------------
__global__ __launch_bounds__(256, 2) void k_gemm() {
    extern __shared__ float sm[];
    // A stages at sm + s*TILE_F (s=0..2); X stages at sm + (3+s)*TILE_F

    const int tid  = threadIdx.x;
    const int wid  = tid >> 5;
    const int lane = tid & 31;
    const int gid  = lane >> 2;
    const int tg   = lane & 3;
    const int wm   = wid >> 2;       // 0..1 -> 64 c-rows
    const int wn   = wid & 3;        // 0..3 -> 32 q-cols

    const int c0 = blockIdx.x * BM;
    const int q0 = blockIdx.y * BNQ;
    const int n    = q0 / QQ;
    const int qloc = q0 - n * QQ;
    const int Rb0  = c0 >> 4;
    const int Nb0  = q0 >> 3;

    const uint32_t sbase = smem_u32(sm);

    auto load_tiles = [&](int kc, int s) {
        #pragma unroll
        for (int u = 0; u < 4; u++) {
            const int i16 = tid + u * 256;
            const int f0  = i16 * 4;
            const int Ra   = f0 >> 9;
            const int rema = f0 & 511;
            const float* ga = g_W2 + ((size_t)(Rb0 + Ra) * 96 + kc * 4) * 128 + rema;
            CP_ASYNC16(sbase + (uint32_t)(s * TILE_F + f0) * 4, ga);
            const int Nbx  = f0 >> 8;
            const int remx = f0 & 255;
            const float* gx = g_XA + ((size_t)(Nb0 + Nbx) * 48 + kc * 2) * 128 + remx;
            CP_ASYNC16(sbase + (uint32_t)((NSTAGE + s) * TILE_F + f0) * 4, gx);
        }
    };

    float acc[4][4][4];
    #pragma unroll
    for (int mf = 0; mf < 4; mf++)
        #pragma unroll
        for (int nf = 0; nf < 4; nf++)
            #pragma unroll
            for (int j = 0; j < 4; j++) acc[mf][nf][j] = 0.f;

    load_tiles(0, 0); CP_COMMIT();
    load_tiles(1, 1); CP_COMMIT();

    #pragma unroll 3
    for (int kc = 0; kc < NKC; kc++) {
        const int s = kc % NSTAGE;
        CP_WAIT1();            // my group for kc is complete
        __syncthreads();       // everyone's data landed; prev compute done
        if (kc + 2 < NKC) load_tiles(kc + 2, (kc + 2) % NSTAGE);
        CP_COMMIT();

        const float* Ab = sm + s * TILE_F;
        const float* Xb = sm + (NSTAGE + s) * TILE_F;
        #pragma unroll
        for (int k16 = 0; k16 < 2; k16++) {
            uint4 bq[4];
            #pragma unroll
            for (int nf = 0; nf < 4; nf++)
                bq[nf] = *(const uint4*)(Xb + (((wn * 4 + nf) * 2 + k16) * 32 + lane) * 4);
            #pragma unroll
            for (int half = 0; half < 2; half++) {
                const int k8 = k16 * 2 + half;
                uint4 aq[4];
                #pragma unroll
                for (int mf = 0; mf < 4; mf++)
                    aq[mf] = *(const uint4*)(Ab + (((wm * 4 + mf) * 4 + k8) * 32 + lane) * 4);
                if (half == 0) {
                    #pragma unroll
                    for (int mf = 0; mf < 4; mf++)
                        #pragma unroll
                        for (int nf = 0; nf < 4; nf++)
                            mma_tf32(acc[mf][nf], aq[mf].x, aq[mf].y, aq[mf].z, aq[mf].w,
                                     bq[nf].x, bq[nf].y);
                } else {
                    #pragma unroll
                    for (int mf = 0; mf < 4; mf++)
                        #pragma unroll
                        for (int nf = 0; nf < 4; nf++)
                            mma_tf32(acc[mf][nf], aq[mf].x, aq[mf].y, aq[mf].z, aq[mf].w,
                                     bq[nf].z, bq[nf].w);
                }
            }
        }
    }

    // ---- epilogue: +zb, z write, BN partials ----
    float s1[4][2], s2[4][2];
    #pragma unroll
    for (int mf = 0; mf < 4; mf++) { s1[mf][0] = s1[mf][1] = 0.f; s2[mf][0] = s2[mf][1] = 0.f; }

    #pragma unroll
    for (int mf = 0; mf < 4; mf++) {
        const int r0 = c0 + wm * 64 + mf * 16 + gid;
        #pragma unroll
        for (int nf = 0; nf < 4; nf++) {
            const int col = qloc + wn * 32 + nf * 8 + tg * 2;
            const int w0 = col % VV;
            const int w1 = (w0 + 1 == VV) ? 0 : w0 + 1;
            const float zb00 = g_zb[r0 * VV + w0],       zb01 = g_zb[r0 * VV + w1];
            const float zb10 = g_zb[(r0 + 8) * VV + w0], zb11 = g_zb[(r0 + 8) * VV + w1];
            float v00 = acc[mf][nf][0] + zb00;
            float v01 = acc[mf][nf][1] + zb01;
            float v10 = acc[mf][nf][2] + zb10;
            float v11 = acc[mf][nf][3] + zb11;
            s1[mf][0] += v00 + v01;  s2[mf][0] += v00 * v00 + v01 * v01;
            s1[mf][1] += v10 + v11;  s2[mf][1] += v10 * v10 + v11 * v11;
            float* zp0 = g_z + (size_t)(n * COUTC + r0) * QQ + col;
            float* zp1 = g_z + (size_t)(n * COUTC + r0 + 8) * QQ + col;
            *(float2*)zp0 = make_float2(v00, v01);
            *(float2*)zp1 = make_float2(v10, v11);
        }
    }
    #pragma unroll
    for (int mf = 0; mf < 4; mf++)
        #pragma unroll
        for (int h = 0; h < 2; h++) {
            s1[mf][h] += __shfl_xor_sync(0xffffffffu, s1[mf][h], 1);
            s1[mf][h] += __shfl_xor_sync(0xffffffffu, s1[mf][h], 2);
            s2[mf][h] += __shfl_xor_sync(0xffffffffu, s2[mf][h], 1);
            s2[mf][h] += __shfl_xor_sync(0xffffffffu, s2[mf][h], 2);
        }
    if (tg == 0) {
        const int slot = blockIdx.y * 4 + wn;
        #pragma unroll
        for (int mf = 0; mf < 4; mf++)
            #pragma unroll
            for (int h = 0; h < 2; h++) {
                const int r = c0 + wm * 64 + mf * 16 + gid + h * 8;
                g_psum[r * NPART + slot] = s1[mf][h];
                g_psq [r * NPART + slot] = s2[mf][h];
            }
    }
}

// ---------------- kernel: finalize BN stats ----------------
__global__ void k_stats(const float* __restrict__ gamma, const float* __restrict__ beta) {
    const int c = blockIdx.x;
    const int tid = threadIdx.x;
    float s1 = 0.f, s2 = 0.f;
    const float* ps = g_psum + c * NPART;
    const float* pq = g_psq  + c * NPART;
    for (int i = tid; i < NPART; i += 256) { s1 += ps[i]; s2 += pq[i]; }
    __shared__ float r1[256], r2[256];
    r1[tid] = s1; r2[tid] = s2;
    __syncthreads();
    for (int s = 128; s > 0; s >>= 1) {
        if (tid < s) { r1[tid] += r1[tid + s]; r2[tid] += r2[tid + s]; }
        __syncthreads();
    }
    if (tid == 0) {
        const float inv  = 1.0f / (float)CNT;
        const float mean = r1[0] * inv;
        const float var  = r2[0] * inv - mean * mean;
        const float sc   = gamma[c] * rsqrtf(var + BN_EPS);
        g_ss[c]         = sc;
        g_ss[COUTC + c] = beta[c] - mean * sc;
    }
}

// ---------------- kernel: normalize + ReLU ----------------
__global__ void k_norm(float* __restrict__ out) {
    const int i4 = blockIdx.x * blockDim.x + threadIdx.x;
    const int c = (i4 / 800) & (COUTC - 1);
    const float sc = g_ss[c];
    const float sh = g_ss[COUTC + c];
    const float4 z = ((const float4*)g_z)[i4];
    float4 o;
    o.x = fmaxf(0.f, fmaf(z.x, sc, sh));
    o.y = fmaxf(0.f, fmaf(z.y, sc, sh));
    o.z = fmaxf(0.f, fmaf(z.z, sc, sh));
    o.w = fmaxf(0.f, fmaf(z.w, sc, sh));
    ((float4*)out)[i4] = o;
}

// ---------------- launch ----------------
extern "C" void kernel_launch(void* const* d_in, const int* in_sizes, int n_in,
                              void* d_out, int out_size) {
    const float* x     = (const float*)d_in[0];
    const float* A     = (const float*)d_in[1];
    const float* W     = (const float*)d_in[2];
    const float* b     = (const float*)d_in[3];
    const float* gamma = (const float*)d_in[4];
    const float* beta  = (const float*)d_in[5];
    float* out = (float*)d_out;

    cudaFuncSetAttribute(k_gemm, cudaFuncAttributeMaxDynamicSharedMemorySize, SMEM_GEMM);

    k_w2  <<<MTOT, 256>>>(W);
    k_zb  <<<VV, 256>>>(A, b);
    k_prep<<<NB * TT, 128>>>(x, A);
    k_gemm<<<dim3(2, NQT2), 256, SMEM_GEMM>>>();
    k_stats<<<COUTC, 256>>>(gamma, beta);
    k_norm<<<(NB * COUTC * TT * VV / 4) / 256, 256>>>(out);
}